// round 14
// baseline (speedup 1.0000x reference)
#include <cuda_runtime.h>
#include <cuda_fp16.h>
#include <cstdint>

// Problem constants
#define NQ    50000
#define MS    50000
#define HN    32
#define KKP   15
#define CINV  64
#define COUTV 128
#define KD    1024          // scratch row length (16 kp x 64 cin); >=960 is zero pad
#define KREAL 960
#define NPAD  50048         // 391 * 128
#define NITER 30            // 960 / 32
#define XELEM (MS * CINV)   // 3.2M
#define XV4   (XELEM / 4)   // 800k float4 groups

// ---------------------------------------------------------------------------
// Scratch (device globals; zero-initialized at load -> padding stays zero)
// ---------------------------------------------------------------------------
__device__ __half g_wf[(size_t)NPAD * KD];           // wf  [n][kd] fp16
__device__ __half g_wt[(size_t)COUTV * KD];          // W^T [cout][kd] fp16
__device__ __half g_xh[(size_t)XELEM];               // x   [m][c] fp16

// ---------------------------------------------------------------------------
// mma / ldmatrix / cp.async helpers (baseline PTX features only)
// ---------------------------------------------------------------------------
__device__ __forceinline__ void ldsm4(uint32_t* r, uint32_t a) {
    asm volatile("ldmatrix.sync.aligned.m8n8.x4.shared.b16 {%0,%1,%2,%3}, [%4];"
                 : "=r"(r[0]), "=r"(r[1]), "=r"(r[2]), "=r"(r[3]) : "r"(a));
}
__device__ __forceinline__ void ldsm4t(uint32_t* r, uint32_t a) {
    asm volatile("ldmatrix.sync.aligned.m8n8.x4.trans.shared.b16 {%0,%1,%2,%3}, [%4];"
                 : "=r"(r[0]), "=r"(r[1]), "=r"(r[2]), "=r"(r[3]) : "r"(a));
}
__device__ __forceinline__ void mma16816h(float* c, const uint32_t* a, const uint32_t* b) {
    asm volatile(
        "mma.sync.aligned.m16n8k16.row.col.f32.f16.f16.f32 "
        "{%0,%1,%2,%3}, {%4,%5,%6,%7}, {%8,%9}, {%0,%1,%2,%3};"
        : "+f"(c[0]), "+f"(c[1]), "+f"(c[2]), "+f"(c[3])
        : "r"(a[0]), "r"(a[1]), "r"(a[2]), "r"(a[3]), "r"(b[0]), "r"(b[1]));
}
__device__ __forceinline__ void cp16(uint32_t saddr, const void* gaddr) {
    asm volatile("cp.async.cg.shared.global [%0], [%1], 16;"
                 :: "r"(saddr), "l"(gaddr) : "memory");
}

// ---------------------------------------------------------------------------
// Kernel 0: prep — x -> fp16 (vectorized float4), W -> W^T fp16
// ---------------------------------------------------------------------------
__global__ __launch_bounds__(256) void kp_prep_all(
    const float* __restrict__ x, const float* __restrict__ W)
{
    const int id = blockIdx.x * 256 + threadIdx.x;
    if (id < XV4) {
        const float4 v = reinterpret_cast<const float4*>(x)[id];
        __half2 p01 = __floats2half2_rn(v.x, v.y);
        __half2 p23 = __floats2half2_rn(v.z, v.w);
        reinterpret_cast<uint2*>(g_xh)[id] =
            make_uint2(*reinterpret_cast<uint32_t*>(&p01),
                       *reinterpret_cast<uint32_t*>(&p23));
    } else {
        const int wi = id - XV4;
        if (wi < COUTV * KD) {
            const int kd = wi & (KD - 1);
            const int co = wi >> 10;
            const float v = (kd < KREAL) ? W[kd * COUTV + co] : 0.0f;
            g_wt[wi] = __float2half_rn(v);
        }
    }
}

// ---------------------------------------------------------------------------
// Kernel 1: tensorized gather. Block = 8 queries / 256 threads.
// Per query: wf[16 kp, 64 c] = wk[16 kp, 32 h] @ x[32 h, 64 c], fp16 mma,
// fp32 accum. x staging is COALESCED: 8 lanes per 128B row -> 4 wavefronts
// per cp.async warp-instr (was 32 with row-per-lane staging).
// ---------------------------------------------------------------------------
#define GQ      8
#define XPITCH  144
#define WKPITCH 80
#define OFF_WK  0
#define OFF_XS  (GQ * 16 * WKPITCH)            // 10240
#define SMEM_GATH (OFF_XS + GQ * HN * XPITCH)  // 10240 + 36864 = 47104

__global__ __launch_bounds__(256, 4) void kpconv_gather_tc(
    const float* __restrict__ q,
    const float* __restrict__ s,
    const int* __restrict__ nb,
    const float* __restrict__ kp)
{
    extern __shared__ char sm[];
    __shared__ float kps[48];
    __shared__ int   idxs[GQ * HN];     // 256 slots, slot = q*32 + h

    const int t    = threadIdx.x;
    const int lane = t & 31;
    const int wid  = t >> 5;
    const int n0   = blockIdx.x * GQ;

    const uint32_t smb  = (uint32_t)__cvta_generic_to_shared(sm);
    const uint32_t wk_s = smb + OFF_WK;
    const uint32_t xs_s = smb + OFF_XS;

    if (t < KKP * 3) kps[t] = kp[t];
    {
        int j = nb[(size_t)n0 * HN + t];          // coalesced: slot t
        j = j < 0 ? 0 : (j >= MS ? MS - 1 : j);
        idxs[t] = j;
    }
    __syncthreads();

    // Phase A: coalesced x staging. Thread covers seg (t&7) of rows
    // (t>>3) + 32u. Each cp.async warp-instr = 4 contiguous 128B rows.
    {
        const int seg = (t & 7) * 16;
        const int r0  = t >> 3;
#pragma unroll
        for (int u = 0; u < 8; u++) {
            const int row = r0 + u * 32;
            const int j = idxs[row];
            cp16(xs_s + row * XPITCH + seg,
                 (const char*)g_xh + (size_t)j * (CINV * 2) + seg);
        }
    }
    asm volatile("cp.async.commit_group;" ::: "memory");

    // Phase B: 15 influence weights for slot t -> wk smem [q][kp][h]
    {
        const int j = idxs[t];
        const int n = n0 + wid;
        const float nx = s[j * 3 + 0] - q[n * 3 + 0];
        const float ny = s[j * 3 + 1] - q[n * 3 + 1];
        const float nz = s[j * 3 + 2] - q[n * 3 + 2];
        __half* wrow = reinterpret_cast<__half*>(sm + OFF_WK) +
                       wid * (16 * WKPITCH / 2) + lane;
#pragma unroll
        for (int k = 0; k < KKP; k++) {
            const float dx = nx - kps[k * 3 + 0];
            const float dy = ny - kps[k * 3 + 1];
            const float dz = nz - kps[k * 3 + 2];
            const float d2 = dx * dx + dy * dy + dz * dz;
            float w = 1.0f - sqrtf(d2) * (1.0f / 0.072f);
            w = w > 0.0f ? w : 0.0f;
            wrow[k * (WKPITCH / 2)] = __float2half_rn(w);
        }
        wrow[15 * (WKPITCH / 2)] = __float2half_rn(0.0f);  // kp pad row
    }
    asm volatile("cp.async.wait_group 0;" ::: "memory");
    __syncthreads();

    // Phase C: warp wid handles query wid.
    const uint32_t brow = ((lane >> 3) & 1) * 8 + (lane & 7);
    const uint32_t bcol = (lane >> 4) * 16;
    const int kp0 = lane >> 2;
    const int cb  = (lane & 3) * 2;
    uint32_t* uo = reinterpret_cast<uint32_t*>(g_wf);

    const int n = n0 + wid;
    const uint32_t wq = wk_s + wid * (16 * WKPITCH);
    const uint32_t xq = xs_s + wid * (HN * XPITCH);

    uint32_t a[2][4];
#pragma unroll
    for (int kc = 0; kc < 2; kc++)
        ldsm4(a[kc], wq + (lane & 15) * WKPITCH + (lane >> 4) * 16 + kc * 32);

    float acc[8][4];
#pragma unroll
    for (int an = 0; an < 8; an++)
#pragma unroll
        for (int e = 0; e < 4; e++) acc[an][e] = 0.0f;

#pragma unroll
    for (int kc = 0; kc < 2; kc++) {
#pragma unroll
        for (int nq = 0; nq < 4; nq++) {
            uint32_t bf[4];
            ldsm4t(bf, xq + (kc * 16 + brow) * XPITCH + bcol + nq * 32);
            mma16816h(acc[nq * 2 + 0], a[kc], bf + 0);
            mma16816h(acc[nq * 2 + 1], a[kc], bf + 2);
        }
    }

    // epilogue: row kp = kp0 (+8), col c = an*8 + cb (+1) -> fp16 pairs
#pragma unroll
    for (int an = 0; an < 8; an++) {
        const int c = an * 8 + cb;
#pragma unroll
        for (int half = 0; half < 2; half++) {
            __half2 p = __floats2half2_rn(acc[an][half * 2 + 0],
                                          acc[an][half * 2 + 1]);
            uo[((size_t)n * KD + (kp0 + half * 8) * 64 + c) >> 1] =
                *reinterpret_cast<uint32_t*>(&p);
        }
    }
}

// ---------------------------------------------------------------------------
// Kernel 2: fp16 mma.sync GEMM  out[N,128] = wf[N,960] @ W[960,128] + bias
// (byte-identical to rounds 9-12 — measured at tail-adjusted mma roofline)
// ---------------------------------------------------------------------------
#define ROWB  80                 // smem bytes per 32-half row (64B + 16B pad)
#define TILEB (128 * ROWB)       // 10240
#define OFF_A  0
#define OFF_B  TILEB
#define BUFB  (2 * TILEB)        // A, B
#define SMEM_GEMM (2 * BUFB + 512)

__global__ __launch_bounds__(256) void kpconv_gemm_mma(
    const float* __restrict__ bias, float* __restrict__ out)
{
    extern __shared__ char sm[];
    const int t    = threadIdx.x;
    const int lane = t & 31;
    const int wid  = t >> 5;
    const int wm   = (wid >> 2) * 64;   // 0 or 64
    const int wn   = (wid & 3) * 32;    // 0,32,64,96
    const int bm   = blockIdx.x * 128;

    float* sbias = reinterpret_cast<float*>(sm + 2 * BUFB);
    if (t < COUTV) sbias[t] = bias[t];

    const uint32_t smb = (uint32_t)__cvta_generic_to_shared(sm);

    const uint4* gA = reinterpret_cast<const uint4*>(g_wf);
    const uint4* gB = reinterpret_cast<const uint4*>(g_wt);

    float acc[4][4][4];
#pragma unroll
    for (int mi = 0; mi < 4; mi++)
#pragma unroll
        for (int ni = 0; ni < 4; ni++)
#pragma unroll
            for (int e = 0; e < 4; e++) acc[mi][ni][e] = 0.0f;

    const int a_r  = lane & 15, a_c = lane >> 4;
    const int b_r4 = ((lane >> 4) & 1) * 8 + (lane & 7);
    const int b_c4 = (lane >> 3) & 1;

    auto prefetch = [&](int it, int buf) {
        const uint32_t base = smb + buf * BUFB;
#pragma unroll
        for (int j = 0; j < 2; j++) {
            const int row = (t + j * 256) >> 2;
            const int seg = t & 3;
            const uint32_t d = base + row * ROWB + seg * 16;
            const size_t ga = (size_t)(bm + row) * (KD / 8) + it * 4 + seg;
            const size_t gb = (size_t)row * (KD / 8) + it * 4 + seg;
            cp16(d + OFF_A, gA + ga);
            cp16(d + OFF_B, gB + gb);
        }
        asm volatile("cp.async.commit_group;" ::: "memory");
    };

    prefetch(0, 0);

    for (int it = 0; it < NITER; it++) {
        const int buf = it & 1;
        if (it + 1 < NITER) {
            prefetch(it + 1, buf ^ 1);
            asm volatile("cp.async.wait_group 1;" ::: "memory");
        } else {
            asm volatile("cp.async.wait_group 0;" ::: "memory");
        }
        __syncthreads();

        const uint32_t base = smb + buf * BUFB;
#pragma unroll
        for (int ks = 0; ks < 2; ks++) {
            uint32_t af[4][4], bf[2][4];
#pragma unroll
            for (int mi = 0; mi < 4; mi++) {
                const uint32_t ao = base + OFF_A +
                    (wm + mi * 16 + a_r) * ROWB + ks * 32 + a_c * 16;
                ldsm4(af[mi], ao);
            }
#pragma unroll
            for (int p = 0; p < 2; p++) {
                const uint32_t bo = base + OFF_B +
                    (wn + p * 16 + b_r4) * ROWB + ks * 32 + b_c4 * 16;
                ldsm4(bf[p], bo);
            }
#pragma unroll
            for (int mi = 0; mi < 4; mi++)
#pragma unroll
                for (int ni = 0; ni < 4; ni++)
                    mma16816h(acc[mi][ni], af[mi], &bf[ni >> 1][(ni & 1) * 2]);
        }
        __syncthreads();
    }

    const int er = lane >> 2;
    const int ec = (lane & 3) * 2;
#pragma unroll
    for (int mi = 0; mi < 4; mi++) {
#pragma unroll
        for (int half = 0; half < 2; half++) {
            const int gm = bm + wm + mi * 16 + er + half * 8;
            if (gm < NQ) {
#pragma unroll
                for (int ni = 0; ni < 4; ni++) {
                    const int nn = wn + ni * 8 + ec;
                    float2 v;
                    v.x = acc[mi][ni][half * 2 + 0] + sbias[nn + 0];
                    v.y = acc[mi][ni][half * 2 + 1] + sbias[nn + 1];
                    *reinterpret_cast<float2*>(out + (size_t)gm * COUTV + nn) = v;
                }
            }
        }
    }
}

// ---------------------------------------------------------------------------
extern "C" void kernel_launch(void* const* d_in, const int* in_sizes, int n_in,
                              void* d_out, int out_size)
{
    const float* q    = (const float*)d_in[0];      // [N,3]
    const float* s    = (const float*)d_in[1];      // [M,3]
    const int*   nb   = (const int*)d_in[2];        // [N,H] int32
    const float* x    = (const float*)d_in[3];      // [M,64]
    const float* kp   = (const float*)d_in[4];      // [15,3]
    const float* w    = (const float*)d_in[5];      // [15,64,128]
    const float* bias = (const float*)d_in[6];      // [128]
    float*       out  = (float*)d_out;              // [N,128]

    cudaFuncSetAttribute(kpconv_gather_tc,
                         cudaFuncAttributeMaxDynamicSharedMemorySize, SMEM_GATH);
    cudaFuncSetAttribute(kpconv_gemm_mma,
                         cudaFuncAttributeMaxDynamicSharedMemorySize, SMEM_GEMM);

    kp_prep_all<<<(XV4 + COUTV * KD + 255) / 256, 256>>>(x, w);
    kpconv_gather_tc<<<NQ / GQ, 256, SMEM_GATH>>>(q, s, nb, kp);
    kpconv_gemm_mma<<<NPAD / 128, 256, SMEM_GEMM>>>(bias, out);
}

// round 15
// speedup vs baseline: 1.0850x; 1.0850x over previous
#include <cuda_runtime.h>
#include <cuda_fp16.h>
#include <cstdint>

// Problem constants
#define NQ    50000
#define MS    50000
#define HN    32
#define KKP   15
#define CINV  64
#define COUTV 128
#define KD    1024          // scratch row length (16 kp x 64 cin); >=960 is zero pad
#define KREAL 960
#define NPAD  50048         // 391 * 128
#define NITER 30            // 960 / 32
#define XELEM (MS * CINV)   // 3.2M
#define XV4   (XELEM / 4)   // 800k float4 groups

// ---------------------------------------------------------------------------
// Scratch (device globals; zero-initialized at load -> padding stays zero)
// ---------------------------------------------------------------------------
__device__ __half g_wf[(size_t)NPAD * KD];           // wf  [n][kd] fp16
__device__ __half g_wt[(size_t)COUTV * KD];          // W^T [cout][kd] fp16
__device__ __half g_xh[(size_t)XELEM];               // x   [m][c] fp16

// ---------------------------------------------------------------------------
// mma / ldmatrix / cp.async helpers (baseline PTX features only)
// ---------------------------------------------------------------------------
__device__ __forceinline__ void ldsm4(uint32_t* r, uint32_t a) {
    asm volatile("ldmatrix.sync.aligned.m8n8.x4.shared.b16 {%0,%1,%2,%3}, [%4];"
                 : "=r"(r[0]), "=r"(r[1]), "=r"(r[2]), "=r"(r[3]) : "r"(a));
}
__device__ __forceinline__ void ldsm4t(uint32_t* r, uint32_t a) {
    asm volatile("ldmatrix.sync.aligned.m8n8.x4.trans.shared.b16 {%0,%1,%2,%3}, [%4];"
                 : "=r"(r[0]), "=r"(r[1]), "=r"(r[2]), "=r"(r[3]) : "r"(a));
}
__device__ __forceinline__ void mma16816h(float* c, const uint32_t* a, const uint32_t* b) {
    asm volatile(
        "mma.sync.aligned.m16n8k16.row.col.f32.f16.f16.f32 "
        "{%0,%1,%2,%3}, {%4,%5,%6,%7}, {%8,%9}, {%0,%1,%2,%3};"
        : "+f"(c[0]), "+f"(c[1]), "+f"(c[2]), "+f"(c[3])
        : "r"(a[0]), "r"(a[1]), "r"(a[2]), "r"(a[3]), "r"(b[0]), "r"(b[1]));
}
__device__ __forceinline__ void cp16(uint32_t saddr, const void* gaddr) {
    asm volatile("cp.async.cg.shared.global [%0], [%1], 16;"
                 :: "r"(saddr), "l"(gaddr) : "memory");
}

// ---------------------------------------------------------------------------
// Kernel 0: prep — x -> fp16 (vectorized float4), W -> W^T fp16
// ---------------------------------------------------------------------------
__global__ __launch_bounds__(256) void kp_prep_all(
    const float* __restrict__ x, const float* __restrict__ W)
{
    const int id = blockIdx.x * 256 + threadIdx.x;
    if (id < XV4) {
        const float4 v = reinterpret_cast<const float4*>(x)[id];
        __half2 p01 = __floats2half2_rn(v.x, v.y);
        __half2 p23 = __floats2half2_rn(v.z, v.w);
        reinterpret_cast<uint2*>(g_xh)[id] =
            make_uint2(*reinterpret_cast<uint32_t*>(&p01),
                       *reinterpret_cast<uint32_t*>(&p23));
    } else {
        const int wi = id - XV4;
        if (wi < COUTV * KD) {
            const int kd = wi & (KD - 1);
            const int co = wi >> 10;
            const float v = (kd < KREAL) ? W[kd * COUTV + co] : 0.0f;
            g_wt[wi] = __float2half_rn(v);
        }
    }
}

// ---------------------------------------------------------------------------
// Kernel 1: tensorized gather. Block = 8 queries / 256 threads.
// Per query: wf[16 kp, 64 c] = wk[16 kp, 32 h] @ x[32 h, 64 c], fp16 mma,
// fp32 accum. x staging coalesced (8 lanes/row). Epilogue staged through
// smem (conflict-free 144B-pitch STS) then coalesced STG.128 -> wavefronts
// per block drop ~1024 -> ~290 for the store path.
// ---------------------------------------------------------------------------
#define GQ      8
#define XPITCH  144
#define WKPITCH 80
#define OFF_WK  0
#define OFF_XS  (GQ * 16 * WKPITCH)            // 10240
#define SMEM_GATH (OFF_XS + GQ * HN * XPITCH)  // 10240 + 36864 = 47104
// epilogue staging reuses the xs region: 128 rows x 144B = 18432 <= 36864

__global__ __launch_bounds__(256, 4) void kpconv_gather_tc(
    const float* __restrict__ q,
    const float* __restrict__ s,
    const int* __restrict__ nb,
    const float* __restrict__ kp)
{
    extern __shared__ char sm[];
    __shared__ float kps[48];
    __shared__ int   idxs[GQ * HN];     // 256 slots, slot = q*32 + h

    const int t    = threadIdx.x;
    const int lane = t & 31;
    const int wid  = t >> 5;
    const int n0   = blockIdx.x * GQ;

    const uint32_t smb  = (uint32_t)__cvta_generic_to_shared(sm);
    const uint32_t wk_s = smb + OFF_WK;
    const uint32_t xs_s = smb + OFF_XS;

    if (t < KKP * 3) kps[t] = kp[t];
    {
        int j = nb[(size_t)n0 * HN + t];          // coalesced: slot t
        j = j < 0 ? 0 : (j >= MS ? MS - 1 : j);
        idxs[t] = j;
    }
    __syncthreads();

    // Phase A: coalesced x staging. Thread covers seg (t&7) of rows
    // (t>>3) + 32u. Each cp.async warp-instr = 4 contiguous 128B rows.
    {
        const int seg = (t & 7) * 16;
        const int r0  = t >> 3;
#pragma unroll
        for (int u = 0; u < 8; u++) {
            const int row = r0 + u * 32;
            const int j = idxs[row];
            cp16(xs_s + row * XPITCH + seg,
                 (const char*)g_xh + (size_t)j * (CINV * 2) + seg);
        }
    }
    asm volatile("cp.async.commit_group;" ::: "memory");

    // Phase B: 15 influence weights for slot t -> wk smem [q][kp][h]
    {
        const int j = idxs[t];
        const int n = n0 + wid;
        const float nx = s[j * 3 + 0] - q[n * 3 + 0];
        const float ny = s[j * 3 + 1] - q[n * 3 + 1];
        const float nz = s[j * 3 + 2] - q[n * 3 + 2];
        __half* wrow = reinterpret_cast<__half*>(sm + OFF_WK) +
                       wid * (16 * WKPITCH / 2) + lane;
#pragma unroll
        for (int k = 0; k < KKP; k++) {
            const float dx = nx - kps[k * 3 + 0];
            const float dy = ny - kps[k * 3 + 1];
            const float dz = nz - kps[k * 3 + 2];
            const float d2 = dx * dx + dy * dy + dz * dz;
            float w = 1.0f - sqrtf(d2) * (1.0f / 0.072f);
            w = w > 0.0f ? w : 0.0f;
            wrow[k * (WKPITCH / 2)] = __float2half_rn(w);
        }
        wrow[15 * (WKPITCH / 2)] = __float2half_rn(0.0f);  // kp pad row
    }
    asm volatile("cp.async.wait_group 0;" ::: "memory");
    __syncthreads();

    // Phase C: warp wid handles query wid.
    const uint32_t brow = ((lane >> 3) & 1) * 8 + (lane & 7);
    const uint32_t bcol = (lane >> 4) * 16;
    const int kp0 = lane >> 2;
    const int cb  = (lane & 3) * 2;

    const uint32_t wq = wk_s + wid * (16 * WKPITCH);
    const uint32_t xq = xs_s + wid * (HN * XPITCH);

    uint32_t a[2][4];
#pragma unroll
    for (int kc = 0; kc < 2; kc++)
        ldsm4(a[kc], wq + (lane & 15) * WKPITCH + (lane >> 4) * 16 + kc * 32);

    float acc[8][4];
#pragma unroll
    for (int an = 0; an < 8; an++)
#pragma unroll
        for (int e = 0; e < 4; e++) acc[an][e] = 0.0f;

#pragma unroll
    for (int kc = 0; kc < 2; kc++) {
#pragma unroll
        for (int nq = 0; nq < 4; nq++) {
            uint32_t bf[4];
            ldsm4t(bf, xq + (kc * 16 + brow) * XPITCH + bcol + nq * 32);
            mma16816h(acc[nq * 2 + 0], a[kc], bf + 0);
            mma16816h(acc[nq * 2 + 1], a[kc], bf + 2);
        }
    }

    // Epilogue 1: all ldsm reads done -> reuse xs region as staging.
    __syncthreads();
    {
        // STS: row (wid*16 + kp0 + half*8), col (an*8 + cb), 144B pitch.
        // Banks: kp0*36 = 4 mod 32 per step, cb/2 adds 0..3 -> conflict-free.
#pragma unroll
        for (int an = 0; an < 8; an++) {
#pragma unroll
            for (int half = 0; half < 2; half++) {
                __half2 p = __floats2half2_rn(acc[an][half * 2 + 0],
                                              acc[an][half * 2 + 1]);
                const uint32_t ad = xs_s +
                    (wid * 16 + kp0 + half * 8) * XPITCH + (an * 8 + cb) * 2;
                asm volatile("st.shared.b32 [%0], %1;"
                             :: "r"(ad), "r"(*reinterpret_cast<uint32_t*>(&p)));
            }
        }
    }
    __syncthreads();

    // Epilogue 2: coalesced copy smem -> g_wf. 128 rows x 128B.
    // Thread: seg (t&7), rows (t>>3)+32u. Warp = 4 consecutive rows (512B).
    {
        const int seg = (t & 7) * 16;
        const int r0  = t >> 3;
        uint4* go = reinterpret_cast<uint4*>(g_wf);
#pragma unroll
        for (int u = 0; u < 4; u++) {
            const int row = r0 + u * 32;          // 0..127 = q*16 + kp
            uint4 v;
            asm volatile("ld.shared.v4.b32 {%0,%1,%2,%3}, [%4];"
                         : "=r"(v.x), "=r"(v.y), "=r"(v.z), "=r"(v.w)
                         : "r"(xs_s + row * XPITCH + seg));
            const int n  = n0 + (row >> 4);
            const int kpr = row & 15;
            go[((size_t)n * KD + kpr * 64) / 8 + (seg >> 4)] = v;
        }
    }
}

// ---------------------------------------------------------------------------
// Kernel 2: fp16 mma.sync GEMM  out[N,128] = wf[N,960] @ W[960,128] + bias
// (byte-identical to rounds 9-14 — measured at tail-adjusted mma roofline)
// ---------------------------------------------------------------------------
#define ROWB  80                 // smem bytes per 32-half row (64B + 16B pad)
#define TILEB (128 * ROWB)       // 10240
#define OFF_A  0
#define OFF_B  TILEB
#define BUFB  (2 * TILEB)        // A, B
#define SMEM_GEMM (2 * BUFB + 512)

__global__ __launch_bounds__(256) void kpconv_gemm_mma(
    const float* __restrict__ bias, float* __restrict__ out)
{
    extern __shared__ char sm[];
    const int t    = threadIdx.x;
    const int lane = t & 31;
    const int wid  = t >> 5;
    const int wm   = (wid >> 2) * 64;   // 0 or 64
    const int wn   = (wid & 3) * 32;    // 0,32,64,96
    const int bm   = blockIdx.x * 128;

    float* sbias = reinterpret_cast<float*>(sm + 2 * BUFB);
    if (t < COUTV) sbias[t] = bias[t];

    const uint32_t smb = (uint32_t)__cvta_generic_to_shared(sm);

    const uint4* gA = reinterpret_cast<const uint4*>(g_wf);
    const uint4* gB = reinterpret_cast<const uint4*>(g_wt);

    float acc[4][4][4];
#pragma unroll
    for (int mi = 0; mi < 4; mi++)
#pragma unroll
        for (int ni = 0; ni < 4; ni++)
#pragma unroll
            for (int e = 0; e < 4; e++) acc[mi][ni][e] = 0.0f;

    const int a_r  = lane & 15, a_c = lane >> 4;
    const int b_r4 = ((lane >> 4) & 1) * 8 + (lane & 7);
    const int b_c4 = (lane >> 3) & 1;

    auto prefetch = [&](int it, int buf) {
        const uint32_t base = smb + buf * BUFB;
#pragma unroll
        for (int j = 0; j < 2; j++) {
            const int row = (t + j * 256) >> 2;
            const int seg = t & 3;
            const uint32_t d = base + row * ROWB + seg * 16;
            const size_t ga = (size_t)(bm + row) * (KD / 8) + it * 4 + seg;
            const size_t gb = (size_t)row * (KD / 8) + it * 4 + seg;
            cp16(d + OFF_A, gA + ga);
            cp16(d + OFF_B, gB + gb);
        }
        asm volatile("cp.async.commit_group;" ::: "memory");
    };

    prefetch(0, 0);

    for (int it = 0; it < NITER; it++) {
        const int buf = it & 1;
        if (it + 1 < NITER) {
            prefetch(it + 1, buf ^ 1);
            asm volatile("cp.async.wait_group 1;" ::: "memory");
        } else {
            asm volatile("cp.async.wait_group 0;" ::: "memory");
        }
        __syncthreads();

        const uint32_t base = smb + buf * BUFB;
#pragma unroll
        for (int ks = 0; ks < 2; ks++) {
            uint32_t af[4][4], bf[2][4];
#pragma unroll
            for (int mi = 0; mi < 4; mi++) {
                const uint32_t ao = base + OFF_A +
                    (wm + mi * 16 + a_r) * ROWB + ks * 32 + a_c * 16;
                ldsm4(af[mi], ao);
            }
#pragma unroll
            for (int p = 0; p < 2; p++) {
                const uint32_t bo = base + OFF_B +
                    (wn + p * 16 + b_r4) * ROWB + ks * 32 + b_c4 * 16;
                ldsm4(bf[p], bo);
            }
#pragma unroll
            for (int mi = 0; mi < 4; mi++)
#pragma unroll
                for (int ni = 0; ni < 4; ni++)
                    mma16816h(acc[mi][ni], af[mi], &bf[ni >> 1][(ni & 1) * 2]);
        }
        __syncthreads();
    }

    const int er = lane >> 2;
    const int ec = (lane & 3) * 2;
#pragma unroll
    for (int mi = 0; mi < 4; mi++) {
#pragma unroll
        for (int half = 0; half < 2; half++) {
            const int gm = bm + wm + mi * 16 + er + half * 8;
            if (gm < NQ) {
#pragma unroll
                for (int ni = 0; ni < 4; ni++) {
                    const int nn = wn + ni * 8 + ec;
                    float2 v;
                    v.x = acc[mi][ni][half * 2 + 0] + sbias[nn + 0];
                    v.y = acc[mi][ni][half * 2 + 1] + sbias[nn + 1];
                    *reinterpret_cast<float2*>(out + (size_t)gm * COUTV + nn) = v;
                }
            }
        }
    }
}

// ---------------------------------------------------------------------------
extern "C" void kernel_launch(void* const* d_in, const int* in_sizes, int n_in,
                              void* d_out, int out_size)
{
    const float* q    = (const float*)d_in[0];      // [N,3]
    const float* s    = (const float*)d_in[1];      // [M,3]
    const int*   nb   = (const int*)d_in[2];        // [N,H] int32
    const float* x    = (const float*)d_in[3];      // [M,64]
    const float* kp   = (const float*)d_in[4];      // [15,3]
    const float* w    = (const float*)d_in[5];      // [15,64,128]
    const float* bias = (const float*)d_in[6];      // [128]
    float*       out  = (float*)d_out;              // [N,128]

    cudaFuncSetAttribute(kpconv_gather_tc,
                         cudaFuncAttributeMaxDynamicSharedMemorySize, SMEM_GATH);
    cudaFuncSetAttribute(kpconv_gemm_mma,
                         cudaFuncAttributeMaxDynamicSharedMemorySize, SMEM_GEMM);

    kp_prep_all<<<(XV4 + COUTV * KD + 255) / 256, 256>>>(x, w);
    kpconv_gather_tc<<<NQ / GQ, 256, SMEM_GATH>>>(q, s, nb, kp);
    kpconv_gemm_mma<<<NPAD / 128, 256, SMEM_GEMM>>>(bias, out);
}

// round 16
// speedup vs baseline: 1.1190x; 1.0314x over previous
#include <cuda_runtime.h>
#include <cuda_fp16.h>
#include <cstdint>

// Problem constants
#define NQ    50000
#define MS    50000
#define HN    32
#define KKP   15
#define CINV  64
#define COUTV 128
#define KD    1024          // scratch row length (16 kp x 64 cin); >=960 is zero pad
#define KREAL 960
#define NPAD  50048         // 391 * 128
#define NITER 30            // 960 / 32
#define XELEM (MS * CINV)   // 3.2M
#define XV4   (XELEM / 4)   // 800k float4 groups
#define WN    (COUTV * KD)  // 131072
#define PREP_TOTAL (XV4 + WN + MS)

// ---------------------------------------------------------------------------
// Scratch (device globals; zero-initialized at load -> padding stays zero)
// ---------------------------------------------------------------------------
__device__ __half g_wf[(size_t)NPAD * KD];           // wf  [n][kd] fp16
__device__ __half g_wt[(size_t)COUTV * KD];          // W^T [cout][kd] fp16
__device__ __half g_xh[(size_t)XELEM];               // x   [m][c] fp16
__device__ float4 g_s4[(size_t)MS];                  // s padded to float4

// ---------------------------------------------------------------------------
// mma / ldmatrix / cp.async helpers (baseline PTX features only)
// ---------------------------------------------------------------------------
__device__ __forceinline__ void ldsm4(uint32_t* r, uint32_t a) {
    asm volatile("ldmatrix.sync.aligned.m8n8.x4.shared.b16 {%0,%1,%2,%3}, [%4];"
                 : "=r"(r[0]), "=r"(r[1]), "=r"(r[2]), "=r"(r[3]) : "r"(a));
}
__device__ __forceinline__ void ldsm4t(uint32_t* r, uint32_t a) {
    asm volatile("ldmatrix.sync.aligned.m8n8.x4.trans.shared.b16 {%0,%1,%2,%3}, [%4];"
                 : "=r"(r[0]), "=r"(r[1]), "=r"(r[2]), "=r"(r[3]) : "r"(a));
}
__device__ __forceinline__ void mma16816h(float* c, const uint32_t* a, const uint32_t* b) {
    asm volatile(
        "mma.sync.aligned.m16n8k16.row.col.f32.f16.f16.f32 "
        "{%0,%1,%2,%3}, {%4,%5,%6,%7}, {%8,%9}, {%0,%1,%2,%3};"
        : "+f"(c[0]), "+f"(c[1]), "+f"(c[2]), "+f"(c[3])
        : "r"(a[0]), "r"(a[1]), "r"(a[2]), "r"(a[3]), "r"(b[0]), "r"(b[1]));
}
__device__ __forceinline__ void cp16(uint32_t saddr, const void* gaddr) {
    asm volatile("cp.async.cg.shared.global [%0], [%1], 16;"
                 :: "r"(saddr), "l"(gaddr) : "memory");
}

// ---------------------------------------------------------------------------
// Kernel 0: prep — x -> fp16, W -> W^T fp16, s -> padded float4
// ---------------------------------------------------------------------------
__global__ __launch_bounds__(256) void kp_prep_all(
    const float* __restrict__ x, const float* __restrict__ W,
    const float* __restrict__ s)
{
    const int id = blockIdx.x * 256 + threadIdx.x;
    if (id < XV4) {
        const float4 v = reinterpret_cast<const float4*>(x)[id];
        __half2 p01 = __floats2half2_rn(v.x, v.y);
        __half2 p23 = __floats2half2_rn(v.z, v.w);
        reinterpret_cast<uint2*>(g_xh)[id] =
            make_uint2(*reinterpret_cast<uint32_t*>(&p01),
                       *reinterpret_cast<uint32_t*>(&p23));
    } else if (id < XV4 + WN) {
        const int wi = id - XV4;
        const int kd = wi & (KD - 1);
        const int co = wi >> 10;
        const float v = (kd < KREAL) ? W[kd * COUTV + co] : 0.0f;
        g_wt[wi] = __float2half_rn(v);
    } else if (id < PREP_TOTAL) {
        const int m = id - XV4 - WN;
        g_s4[m] = make_float4(s[m * 3 + 0], s[m * 3 + 1], s[m * 3 + 2], 0.0f);
    }
}

// ---------------------------------------------------------------------------
// Kernel 1: tensorized gather. Block = 8 queries / 256 threads.
// Per query: wf[16 kp, 64 c] = wk[16 kp, 32 h] @ x[32 h, 64 c], fp16 mma,
// fp32 accum. x staging coalesced; s gathered as single LDG.128 (padded
// float4); epilogue staged through smem then coalesced STG.128.
// ---------------------------------------------------------------------------
#define GQ      8
#define XPITCH  144
#define WKPITCH 80
#define OFF_WK  0
#define OFF_XS  (GQ * 16 * WKPITCH)            // 10240
#define SMEM_GATH (OFF_XS + GQ * HN * XPITCH)  // 10240 + 36864 = 47104

__global__ __launch_bounds__(256, 4) void kpconv_gather_tc(
    const float* __restrict__ q,
    const int* __restrict__ nb,
    const float* __restrict__ kp)
{
    extern __shared__ char sm[];
    __shared__ float kps[48];
    __shared__ int   idxs[GQ * HN];     // 256 slots, slot = q*32 + h

    const int t    = threadIdx.x;
    const int lane = t & 31;
    const int wid  = t >> 5;
    const int n0   = blockIdx.x * GQ;

    const uint32_t smb  = (uint32_t)__cvta_generic_to_shared(sm);
    const uint32_t wk_s = smb + OFF_WK;
    const uint32_t xs_s = smb + OFF_XS;

    if (t < KKP * 3) kps[t] = kp[t];
    {
        int j = nb[(size_t)n0 * HN + t];          // coalesced: slot t
        j = j < 0 ? 0 : (j >= MS ? MS - 1 : j);
        idxs[t] = j;
    }
    __syncthreads();

    // Phase A: coalesced x staging. Thread covers seg (t&7) of rows
    // (t>>3) + 32u. Each cp.async warp-instr = 4 contiguous 128B rows.
    {
        const int seg = (t & 7) * 16;
        const int r0  = t >> 3;
#pragma unroll
        for (int u = 0; u < 8; u++) {
            const int row = r0 + u * 32;
            const int j = idxs[row];
            cp16(xs_s + row * XPITCH + seg,
                 (const char*)g_xh + (size_t)j * (CINV * 2) + seg);
        }
    }
    asm volatile("cp.async.commit_group;" ::: "memory");

    // Phase B: 15 influence weights for slot t -> wk smem [q][kp][h]
    {
        const int j = idxs[t];
        const int n = n0 + wid;
        const float4 sv = g_s4[j];               // single LDG.128
        const float nx = sv.x - q[n * 3 + 0];
        const float ny = sv.y - q[n * 3 + 1];
        const float nz = sv.z - q[n * 3 + 2];
        __half* wrow = reinterpret_cast<__half*>(sm + OFF_WK) +
                       wid * (16 * WKPITCH / 2) + lane;
#pragma unroll
        for (int k = 0; k < KKP; k++) {
            const float dx = nx - kps[k * 3 + 0];
            const float dy = ny - kps[k * 3 + 1];
            const float dz = nz - kps[k * 3 + 2];
            const float d2 = dx * dx + dy * dy + dz * dz;
            float w = 1.0f - sqrtf(d2) * (1.0f / 0.072f);
            w = w > 0.0f ? w : 0.0f;
            wrow[k * (WKPITCH / 2)] = __float2half_rn(w);
        }
        wrow[15 * (WKPITCH / 2)] = __float2half_rn(0.0f);  // kp pad row
    }
    asm volatile("cp.async.wait_group 0;" ::: "memory");
    __syncthreads();

    // Phase C: warp wid handles query wid.
    const uint32_t brow = ((lane >> 3) & 1) * 8 + (lane & 7);
    const uint32_t bcol = (lane >> 4) * 16;
    const int kp0 = lane >> 2;
    const int cb  = (lane & 3) * 2;

    const uint32_t wq = wk_s + wid * (16 * WKPITCH);
    const uint32_t xq = xs_s + wid * (HN * XPITCH);

    uint32_t a[2][4];
#pragma unroll
    for (int kc = 0; kc < 2; kc++)
        ldsm4(a[kc], wq + (lane & 15) * WKPITCH + (lane >> 4) * 16 + kc * 32);

    float acc[8][4];
#pragma unroll
    for (int an = 0; an < 8; an++)
#pragma unroll
        for (int e = 0; e < 4; e++) acc[an][e] = 0.0f;

#pragma unroll
    for (int kc = 0; kc < 2; kc++) {
#pragma unroll
        for (int nq = 0; nq < 4; nq++) {
            uint32_t bf[4];
            ldsm4t(bf, xq + (kc * 16 + brow) * XPITCH + bcol + nq * 32);
            mma16816h(acc[nq * 2 + 0], a[kc], bf + 0);
            mma16816h(acc[nq * 2 + 1], a[kc], bf + 2);
        }
    }

    // Epilogue 1: all ldsm reads done -> reuse xs region as staging.
    __syncthreads();
    {
#pragma unroll
        for (int an = 0; an < 8; an++) {
#pragma unroll
            for (int half = 0; half < 2; half++) {
                __half2 p = __floats2half2_rn(acc[an][half * 2 + 0],
                                              acc[an][half * 2 + 1]);
                const uint32_t ad = xs_s +
                    (wid * 16 + kp0 + half * 8) * XPITCH + (an * 8 + cb) * 2;
                asm volatile("st.shared.b32 [%0], %1;"
                             :: "r"(ad), "r"(*reinterpret_cast<uint32_t*>(&p)));
            }
        }
    }
    __syncthreads();

    // Epilogue 2: coalesced copy smem -> g_wf. 128 rows x 128B.
    {
        const int seg = (t & 7) * 16;
        const int r0  = t >> 3;
        uint4* go = reinterpret_cast<uint4*>(g_wf);
#pragma unroll
        for (int u = 0; u < 4; u++) {
            const int row = r0 + u * 32;          // 0..127 = q*16 + kp
            uint4 v;
            asm volatile("ld.shared.v4.b32 {%0,%1,%2,%3}, [%4];"
                         : "=r"(v.x), "=r"(v.y), "=r"(v.z), "=r"(v.w)
                         : "r"(xs_s + row * XPITCH + seg));
            const int n  = n0 + (row >> 4);
            const int kpr = row & 15;
            go[((size_t)n * KD + kpr * 64) / 8 + (seg >> 4)] = v;
        }
    }
}

// ---------------------------------------------------------------------------
// Kernel 2: fp16 mma.sync GEMM  out[N,128] = wf[N,960] @ W[960,128] + bias
// (byte-identical to rounds 9-15 — measured at tail-adjusted mma roofline)
// ---------------------------------------------------------------------------
#define ROWB  80                 // smem bytes per 32-half row (64B + 16B pad)
#define TILEB (128 * ROWB)       // 10240
#define OFF_A  0
#define OFF_B  TILEB
#define BUFB  (2 * TILEB)        // A, B
#define SMEM_GEMM (2 * BUFB + 512)

__global__ __launch_bounds__(256) void kpconv_gemm_mma(
    const float* __restrict__ bias, float* __restrict__ out)
{
    extern __shared__ char sm[];
    const int t    = threadIdx.x;
    const int lane = t & 31;
    const int wid  = t >> 5;
    const int wm   = (wid >> 2) * 64;   // 0 or 64
    const int wn   = (wid & 3) * 32;    // 0,32,64,96
    const int bm   = blockIdx.x * 128;

    float* sbias = reinterpret_cast<float*>(sm + 2 * BUFB);
    if (t < COUTV) sbias[t] = bias[t];

    const uint32_t smb = (uint32_t)__cvta_generic_to_shared(sm);

    const uint4* gA = reinterpret_cast<const uint4*>(g_wf);
    const uint4* gB = reinterpret_cast<const uint4*>(g_wt);

    float acc[4][4][4];
#pragma unroll
    for (int mi = 0; mi < 4; mi++)
#pragma unroll
        for (int ni = 0; ni < 4; ni++)
#pragma unroll
            for (int e = 0; e < 4; e++) acc[mi][ni][e] = 0.0f;

    const int a_r  = lane & 15, a_c = lane >> 4;
    const int b_r4 = ((lane >> 4) & 1) * 8 + (lane & 7);
    const int b_c4 = (lane >> 3) & 1;

    auto prefetch = [&](int it, int buf) {
        const uint32_t base = smb + buf * BUFB;
#pragma unroll
        for (int j = 0; j < 2; j++) {
            const int row = (t + j * 256) >> 2;
            const int seg = t & 3;
            const uint32_t d = base + row * ROWB + seg * 16;
            const size_t ga = (size_t)(bm + row) * (KD / 8) + it * 4 + seg;
            const size_t gb = (size_t)row * (KD / 8) + it * 4 + seg;
            cp16(d + OFF_A, gA + ga);
            cp16(d + OFF_B, gB + gb);
        }
        asm volatile("cp.async.commit_group;" ::: "memory");
    };

    prefetch(0, 0);

    for (int it = 0; it < NITER; it++) {
        const int buf = it & 1;
        if (it + 1 < NITER) {
            prefetch(it + 1, buf ^ 1);
            asm volatile("cp.async.wait_group 1;" ::: "memory");
        } else {
            asm volatile("cp.async.wait_group 0;" ::: "memory");
        }
        __syncthreads();

        const uint32_t base = smb + buf * BUFB;
#pragma unroll
        for (int ks = 0; ks < 2; ks++) {
            uint32_t af[4][4], bf[2][4];
#pragma unroll
            for (int mi = 0; mi < 4; mi++) {
                const uint32_t ao = base + OFF_A +
                    (wm + mi * 16 + a_r) * ROWB + ks * 32 + a_c * 16;
                ldsm4(af[mi], ao);
            }
#pragma unroll
            for (int p = 0; p < 2; p++) {
                const uint32_t bo = base + OFF_B +
                    (wn + p * 16 + b_r4) * ROWB + ks * 32 + b_c4 * 16;
                ldsm4(bf[p], bo);
            }
#pragma unroll
            for (int mi = 0; mi < 4; mi++)
#pragma unroll
                for (int ni = 0; ni < 4; ni++)
                    mma16816h(acc[mi][ni], af[mi], &bf[ni >> 1][(ni & 1) * 2]);
        }
        __syncthreads();
    }

    const int er = lane >> 2;
    const int ec = (lane & 3) * 2;
#pragma unroll
    for (int mi = 0; mi < 4; mi++) {
#pragma unroll
        for (int half = 0; half < 2; half++) {
            const int gm = bm + wm + mi * 16 + er + half * 8;
            if (gm < NQ) {
#pragma unroll
                for (int ni = 0; ni < 4; ni++) {
                    const int nn = wn + ni * 8 + ec;
                    float2 v;
                    v.x = acc[mi][ni][half * 2 + 0] + sbias[nn + 0];
                    v.y = acc[mi][ni][half * 2 + 1] + sbias[nn + 1];
                    *reinterpret_cast<float2*>(out + (size_t)gm * COUTV + nn) = v;
                }
            }
        }
    }
}

// ---------------------------------------------------------------------------
extern "C" void kernel_launch(void* const* d_in, const int* in_sizes, int n_in,
                              void* d_out, int out_size)
{
    const float* q    = (const float*)d_in[0];      // [N,3]
    const float* s    = (const float*)d_in[1];      // [M,3]
    const int*   nb   = (const int*)d_in[2];        // [N,H] int32
    const float* x    = (const float*)d_in[3];      // [M,64]
    const float* kp   = (const float*)d_in[4];      // [15,3]
    const float* w    = (const float*)d_in[5];      // [15,64,128]
    const float* bias = (const float*)d_in[6];      // [128]
    float*       out  = (float*)d_out;              // [N,128]

    cudaFuncSetAttribute(kpconv_gather_tc,
                         cudaFuncAttributeMaxDynamicSharedMemorySize, SMEM_GATH);
    cudaFuncSetAttribute(kpconv_gemm_mma,
                         cudaFuncAttributeMaxDynamicSharedMemorySize, SMEM_GEMM);

    kp_prep_all<<<(PREP_TOTAL + 255) / 256, 256>>>(x, w, s);
    kpconv_gather_tc<<<NQ / GQ, 256, SMEM_GATH>>>(q, nb, kp);
    kpconv_gemm_mma<<<NPAD / 128, 256, SMEM_GEMM>>>(bias, out);
}

// round 17
// speedup vs baseline: 1.1361x; 1.0152x over previous
#include <cuda_runtime.h>
#include <cuda_fp16.h>
#include <cstdint>

// Problem constants
#define NQ    50000
#define MS    50000
#define HN    32
#define KKP   15
#define CINV  64
#define COUTV 128
#define KD    1024          // scratch row length (16 kp x 64 cin); >=960 is zero pad
#define KREAL 960
#define NPAD  50048         // 391 * 128
#define NITER 30            // 960 / 32
#define XELEM (MS * CINV)   // 3.2M
#define XV4   (XELEM / 4)   // 800k float4 groups
#define WN    (COUTV * KD)  // 131072
#define PREP_TOTAL (XV4 + WN + MS)

// ---------------------------------------------------------------------------
// Scratch (device globals; zero-initialized at load -> padding stays zero)
// ---------------------------------------------------------------------------
__device__ __half g_wf[(size_t)NPAD * KD];           // wf  [n][kd] fp16
__device__ __half g_wt[(size_t)COUTV * KD];          // W^T [cout][kd] fp16
__device__ __half g_xh[(size_t)XELEM];               // x   [m][c] fp16
__device__ float4 g_s4[(size_t)MS];                  // s padded to float4

// ---------------------------------------------------------------------------
// mma / ldmatrix / cp.async helpers (baseline PTX features only)
// ---------------------------------------------------------------------------
__device__ __forceinline__ void ldsm4(uint32_t* r, uint32_t a) {
    asm volatile("ldmatrix.sync.aligned.m8n8.x4.shared.b16 {%0,%1,%2,%3}, [%4];"
                 : "=r"(r[0]), "=r"(r[1]), "=r"(r[2]), "=r"(r[3]) : "r"(a));
}
__device__ __forceinline__ void ldsm4t(uint32_t* r, uint32_t a) {
    asm volatile("ldmatrix.sync.aligned.m8n8.x4.trans.shared.b16 {%0,%1,%2,%3}, [%4];"
                 : "=r"(r[0]), "=r"(r[1]), "=r"(r[2]), "=r"(r[3]) : "r"(a));
}
__device__ __forceinline__ void mma16816h(float* c, const uint32_t* a, const uint32_t* b) {
    asm volatile(
        "mma.sync.aligned.m16n8k16.row.col.f32.f16.f16.f32 "
        "{%0,%1,%2,%3}, {%4,%5,%6,%7}, {%8,%9}, {%0,%1,%2,%3};"
        : "+f"(c[0]), "+f"(c[1]), "+f"(c[2]), "+f"(c[3])
        : "r"(a[0]), "r"(a[1]), "r"(a[2]), "r"(a[3]), "r"(b[0]), "r"(b[1]));
}
__device__ __forceinline__ void cp16(uint32_t saddr, const void* gaddr) {
    asm volatile("cp.async.cg.shared.global [%0], [%1], 16;"
                 :: "r"(saddr), "l"(gaddr) : "memory");
}

// ---------------------------------------------------------------------------
// Kernel 0: prep — x -> fp16, W -> W^T fp16, s -> padded float4
// ---------------------------------------------------------------------------
__global__ __launch_bounds__(256) void kp_prep_all(
    const float* __restrict__ x, const float* __restrict__ W,
    const float* __restrict__ s)
{
    const int id = blockIdx.x * 256 + threadIdx.x;
    if (id < XV4) {
        const float4 v = reinterpret_cast<const float4*>(x)[id];
        __half2 p01 = __floats2half2_rn(v.x, v.y);
        __half2 p23 = __floats2half2_rn(v.z, v.w);
        reinterpret_cast<uint2*>(g_xh)[id] =
            make_uint2(*reinterpret_cast<uint32_t*>(&p01),
                       *reinterpret_cast<uint32_t*>(&p23));
    } else if (id < XV4 + WN) {
        const int wi = id - XV4;
        const int kd = wi & (KD - 1);
        const int co = wi >> 10;
        const float v = (kd < KREAL) ? W[kd * COUTV + co] : 0.0f;
        g_wt[wi] = __float2half_rn(v);
    } else if (id < PREP_TOTAL) {
        const int m = id - XV4 - WN;
        g_s4[m] = make_float4(s[m * 3 + 0], s[m * 3 + 1], s[m * 3 + 2], 0.0f);
    }
}

// ---------------------------------------------------------------------------
// Kernel 1: tensorized gather. Block = 8 queries / 256 threads.
// (byte-identical to round 16 — measured ~56us, near issue/latency floor)
// ---------------------------------------------------------------------------
#define GQ      8
#define XPITCH  144
#define WKPITCH 80
#define OFF_WK  0
#define OFF_XS  (GQ * 16 * WKPITCH)            // 10240
#define SMEM_GATH (OFF_XS + GQ * HN * XPITCH)  // 10240 + 36864 = 47104

__global__ __launch_bounds__(256, 4) void kpconv_gather_tc(
    const float* __restrict__ q,
    const int* __restrict__ nb,
    const float* __restrict__ kp)
{
    extern __shared__ char sm[];
    __shared__ float kps[48];
    __shared__ int   idxs[GQ * HN];     // 256 slots, slot = q*32 + h

    const int t    = threadIdx.x;
    const int lane = t & 31;
    const int wid  = t >> 5;
    const int n0   = blockIdx.x * GQ;

    const uint32_t smb  = (uint32_t)__cvta_generic_to_shared(sm);
    const uint32_t wk_s = smb + OFF_WK;
    const uint32_t xs_s = smb + OFF_XS;

    if (t < KKP * 3) kps[t] = kp[t];
    {
        int j = nb[(size_t)n0 * HN + t];          // coalesced: slot t
        j = j < 0 ? 0 : (j >= MS ? MS - 1 : j);
        idxs[t] = j;
    }
    __syncthreads();

    // Phase A: coalesced x staging (8 lanes per 128B row).
    {
        const int seg = (t & 7) * 16;
        const int r0  = t >> 3;
#pragma unroll
        for (int u = 0; u < 8; u++) {
            const int row = r0 + u * 32;
            const int j = idxs[row];
            cp16(xs_s + row * XPITCH + seg,
                 (const char*)g_xh + (size_t)j * (CINV * 2) + seg);
        }
    }
    asm volatile("cp.async.commit_group;" ::: "memory");

    // Phase B: 15 influence weights for slot t -> wk smem [q][kp][h]
    {
        const int j = idxs[t];
        const int n = n0 + wid;
        const float4 sv = g_s4[j];               // single LDG.128
        const float nx = sv.x - q[n * 3 + 0];
        const float ny = sv.y - q[n * 3 + 1];
        const float nz = sv.z - q[n * 3 + 2];
        __half* wrow = reinterpret_cast<__half*>(sm + OFF_WK) +
                       wid * (16 * WKPITCH / 2) + lane;
#pragma unroll
        for (int k = 0; k < KKP; k++) {
            const float dx = nx - kps[k * 3 + 0];
            const float dy = ny - kps[k * 3 + 1];
            const float dz = nz - kps[k * 3 + 2];
            const float d2 = dx * dx + dy * dy + dz * dz;
            float w = 1.0f - sqrtf(d2) * (1.0f / 0.072f);
            w = w > 0.0f ? w : 0.0f;
            wrow[k * (WKPITCH / 2)] = __float2half_rn(w);
        }
        wrow[15 * (WKPITCH / 2)] = __float2half_rn(0.0f);  // kp pad row
    }
    asm volatile("cp.async.wait_group 0;" ::: "memory");
    __syncthreads();

    // Phase C: warp wid handles query wid.
    const uint32_t brow = ((lane >> 3) & 1) * 8 + (lane & 7);
    const uint32_t bcol = (lane >> 4) * 16;
    const int kp0 = lane >> 2;
    const int cb  = (lane & 3) * 2;

    const uint32_t wq = wk_s + wid * (16 * WKPITCH);
    const uint32_t xq = xs_s + wid * (HN * XPITCH);

    uint32_t a[2][4];
#pragma unroll
    for (int kc = 0; kc < 2; kc++)
        ldsm4(a[kc], wq + (lane & 15) * WKPITCH + (lane >> 4) * 16 + kc * 32);

    float acc[8][4];
#pragma unroll
    for (int an = 0; an < 8; an++)
#pragma unroll
        for (int e = 0; e < 4; e++) acc[an][e] = 0.0f;

#pragma unroll
    for (int kc = 0; kc < 2; kc++) {
#pragma unroll
        for (int nq = 0; nq < 4; nq++) {
            uint32_t bf[4];
            ldsm4t(bf, xq + (kc * 16 + brow) * XPITCH + bcol + nq * 32);
            mma16816h(acc[nq * 2 + 0], a[kc], bf + 0);
            mma16816h(acc[nq * 2 + 1], a[kc], bf + 2);
        }
    }

    // Epilogue 1: all ldsm reads done -> reuse xs region as staging.
    __syncthreads();
    {
#pragma unroll
        for (int an = 0; an < 8; an++) {
#pragma unroll
            for (int half = 0; half < 2; half++) {
                __half2 p = __floats2half2_rn(acc[an][half * 2 + 0],
                                              acc[an][half * 2 + 1]);
                const uint32_t ad = xs_s +
                    (wid * 16 + kp0 + half * 8) * XPITCH + (an * 8 + cb) * 2;
                asm volatile("st.shared.b32 [%0], %1;"
                             :: "r"(ad), "r"(*reinterpret_cast<uint32_t*>(&p)));
            }
        }
    }
    __syncthreads();

    // Epilogue 2: coalesced copy smem -> g_wf. 128 rows x 128B.
    {
        const int seg = (t & 7) * 16;
        const int r0  = t >> 3;
        uint4* go = reinterpret_cast<uint4*>(g_wf);
#pragma unroll
        for (int u = 0; u < 4; u++) {
            const int row = r0 + u * 32;          // 0..127 = q*16 + kp
            uint4 v;
            asm volatile("ld.shared.v4.b32 {%0,%1,%2,%3}, [%4];"
                         : "=r"(v.x), "=r"(v.y), "=r"(v.z), "=r"(v.w)
                         : "r"(xs_s + row * XPITCH + seg));
            const int n  = n0 + (row >> 4);
            const int kpr = row & 15;
            go[((size_t)n * KD + kpr * 64) / 8 + (seg >> 4)] = v;
        }
    }
}

// ---------------------------------------------------------------------------
// Kernel 2: fp16 mma.sync GEMM  out[N,128] = wf[N,960] @ W[960,128] + bias
// Block tile 128x128, 8 warps, BK=32.
// NEW: 4-stage cp.async pipeline, ONE barrier per iteration (was 2), loads
// land 2 iterations ahead of use -> L2 latency off the critical path.
// ---------------------------------------------------------------------------
#define ROWB   80                // smem bytes per 32-half row (64B + 16B pad)
#define TILEB  (128 * ROWB)      // 10240
#define OFF_A  0
#define OFF_B  TILEB
#define STAGEB (2 * TILEB)       // A + B per stage = 20480
#define NSTAGE 4
#define SMEM_GEMM (NSTAGE * STAGEB + 512)

__global__ __launch_bounds__(256) void kpconv_gemm_mma(
    const float* __restrict__ bias, float* __restrict__ out)
{
    extern __shared__ char sm[];
    const int t    = threadIdx.x;
    const int lane = t & 31;
    const int wid  = t >> 5;
    const int wm   = (wid >> 2) * 64;   // 0 or 64
    const int wn   = (wid & 3) * 32;    // 0,32,64,96
    const int bm   = blockIdx.x * 128;

    float* sbias = reinterpret_cast<float*>(sm + NSTAGE * STAGEB);
    if (t < COUTV) sbias[t] = bias[t];

    const uint32_t smb = (uint32_t)__cvta_generic_to_shared(sm);

    const uint4* gA = reinterpret_cast<const uint4*>(g_wf);
    const uint4* gB = reinterpret_cast<const uint4*>(g_wt);

    float acc[4][4][4];
#pragma unroll
    for (int mi = 0; mi < 4; mi++)
#pragma unroll
        for (int ni = 0; ni < 4; ni++)
#pragma unroll
            for (int e = 0; e < 4; e++) acc[mi][ni][e] = 0.0f;

    const int a_r  = lane & 15, a_c = lane >> 4;
    const int b_r4 = ((lane >> 4) & 1) * 8 + (lane & 7);
    const int b_c4 = (lane >> 3) & 1;

    auto prefetch = [&](int it, int stg) {
        const uint32_t base = smb + stg * STAGEB;
#pragma unroll
        for (int j = 0; j < 2; j++) {
            const int row = (t + j * 256) >> 2;
            const int seg = t & 3;
            const uint32_t d = base + row * ROWB + seg * 16;
            const size_t ga = (size_t)(bm + row) * (KD / 8) + it * 4 + seg;
            const size_t gb = (size_t)row * (KD / 8) + it * 4 + seg;
            cp16(d + OFF_A, gA + ga);
            cp16(d + OFF_B, gB + gb);
        }
        asm volatile("cp.async.commit_group;" ::: "memory");
    };

    prefetch(0, 0);
    prefetch(1, 1);

    for (int it = 0; it < NITER; it++) {
        if (it + 2 < NITER) {
            prefetch(it + 2, (it + 2) & (NSTAGE - 1));
            asm volatile("cp.async.wait_group 2;" ::: "memory");
        } else if (it + 1 < NITER) {
            asm volatile("cp.async.wait_group 1;" ::: "memory");
        } else {
            asm volatile("cp.async.wait_group 0;" ::: "memory");
        }
        __syncthreads();   // single barrier: data visible + stage-reuse safe

        const uint32_t base = smb + (it & (NSTAGE - 1)) * STAGEB;
#pragma unroll
        for (int ks = 0; ks < 2; ks++) {
            uint32_t af[4][4], bf[2][4];
#pragma unroll
            for (int mi = 0; mi < 4; mi++) {
                const uint32_t ao = base + OFF_A +
                    (wm + mi * 16 + a_r) * ROWB + ks * 32 + a_c * 16;
                ldsm4(af[mi], ao);
            }
#pragma unroll
            for (int p = 0; p < 2; p++) {
                const uint32_t bo = base + OFF_B +
                    (wn + p * 16 + b_r4) * ROWB + ks * 32 + b_c4 * 16;
                ldsm4(bf[p], bo);
            }
#pragma unroll
            for (int mi = 0; mi < 4; mi++)
#pragma unroll
                for (int ni = 0; ni < 4; ni++)
                    mma16816h(acc[mi][ni], af[mi], &bf[ni >> 1][(ni & 1) * 2]);
        }
    }

    const int er = lane >> 2;
    const int ec = (lane & 3) * 2;
#pragma unroll
    for (int mi = 0; mi < 4; mi++) {
#pragma unroll
        for (int half = 0; half < 2; half++) {
            const int gm = bm + wm + mi * 16 + er + half * 8;
            if (gm < NQ) {
#pragma unroll
                for (int ni = 0; ni < 4; ni++) {
                    const int nn = wn + ni * 8 + ec;
                    float2 v;
                    v.x = acc[mi][ni][half * 2 + 0] + sbias[nn + 0];
                    v.y = acc[mi][ni][half * 2 + 1] + sbias[nn + 1];
                    *reinterpret_cast<float2*>(out + (size_t)gm * COUTV + nn) = v;
                }
            }
        }
    }
}

// ---------------------------------------------------------------------------
extern "C" void kernel_launch(void* const* d_in, const int* in_sizes, int n_in,
                              void* d_out, int out_size)
{
    const float* q    = (const float*)d_in[0];      // [N,3]
    const float* s    = (const float*)d_in[1];      // [M,3]
    const int*   nb   = (const int*)d_in[2];        // [N,H] int32
    const float* x    = (const float*)d_in[3];      // [M,64]
    const float* kp   = (const float*)d_in[4];      // [15,3]
    const float* w    = (const float*)d_in[5];      // [15,64,128]
    const float* bias = (const float*)d_in[6];      // [128]
    float*       out  = (float*)d_out;              // [N,128]

    cudaFuncSetAttribute(kpconv_gather_tc,
                         cudaFuncAttributeMaxDynamicSharedMemorySize, SMEM_GATH);
    cudaFuncSetAttribute(kpconv_gemm_mma,
                         cudaFuncAttributeMaxDynamicSharedMemorySize, SMEM_GEMM);

    kp_prep_all<<<(PREP_TOTAL + 255) / 256, 256>>>(x, w, s);
    kpconv_gather_tc<<<NQ / GQ, 256, SMEM_GATH>>>(q, nb, kp);
    kpconv_gemm_mma<<<NPAD / 128, 256, SMEM_GEMM>>>(bias, out);
}